// round 11
// baseline (speedup 1.0000x reference)
#include <cuda_runtime.h>
#include <cuda_fp16.h>

// ListMLE: B=8192 rows, N=4096, labels int32.
//   result = [ Σ_j log(S_j) - Σ x ] / (B*N),  S_j = cumsum_j exp(x[label[j]])
// Round-11: persistent double-buffered blocks. Raw fp32 outputs row is staged
// into smem via cp.async.cg (register-free, L1-bypassing); while a block
// gathers/scans row r, row r+GRID streams into the other buffer -> DRAM and
// L1tex phases overlap structurally. exp() moves after the gather (same MUFU
// count); Σx computed from gathered values (same set as the row). Logs fused
// per 4 (prod of 4 prefix sums < 2.4e15). 820 persistent blocks, ~10 rows
// each. Fused deterministic fp64 finalize via fence+counter.

#define B_ROWS  8192
#define N_COLS  4096
#define THREADS 256
#define CHUNK   16
#define NWARPS  (THREADS / 32)   // 8
#define GRID    820              // one wave at 6 blocks/SM on 148 SMs
#define LN2F    0.6931471805599453f

__device__ float        g_partial[B_ROWS];
__device__ unsigned int g_count = 0;

__device__ __forceinline__ void cp16(unsigned dst, const void* src) {
    asm volatile("cp.async.cg.shared.global [%0], [%1], 16;" :: "r"(dst), "l"(src));
}
__device__ __forceinline__ void cp_commit() {
    asm volatile("cp.async.commit_group;");
}
template <int N>
__device__ __forceinline__ void cp_wait() {
    asm volatile("cp.async.wait_group %0;" :: "n"(N));
}

__global__ __launch_bounds__(THREADS, 6)
void listmle_main(const float* __restrict__ outputs,
                  const int* __restrict__ labels,
                  float* __restrict__ out) {
    __shared__ float  x_s[2][N_COLS];        // 32 KB: double-buffered raw rows
    __shared__ float  warp_tot[NWARPS];
    __shared__ float  red_s[NWARPS];
    __shared__ double sd[NWARPS];
    __shared__ bool   is_last;

    const int t = threadIdx.x, lane = t & 31, wid = t >> 5;
    const unsigned full = 0xFFFFFFFFu;
    const unsigned sb0 = (unsigned)__cvta_generic_to_shared(&x_s[0][0]);
    const unsigned sb1 = (unsigned)__cvta_generic_to_shared(&x_s[1][0]);

    // ---- prologue: prefetch first row into buffer 0 ----
    {
        const char* src = (const char*)(outputs + (size_t)blockIdx.x * N_COLS);
        #pragma unroll
        for (int k = 0; k < 4; k++) {
            unsigned off = (unsigned)(t + k * THREADS) * 16u;
            cp16(sb0 + off, src + off);
        }
        cp_commit();
    }

    int buf = 0;
    for (int row = blockIdx.x; row < B_ROWS; row += GRID, buf ^= 1) {
        // ---- prefetch next row into the other buffer, then wait for current ----
        int nrow = row + GRID;
        if (nrow < B_ROWS) {
            unsigned nb = buf ? sb0 : sb1;
            const char* src = (const char*)(outputs + (size_t)nrow * N_COLS);
            #pragma unroll
            for (int k = 0; k < 4; k++) {
                unsigned off = (unsigned)(t + k * THREADS) * 16u;
                cp16(nb + off, src + off);
            }
            cp_commit();
            cp_wait<1>();          // current row's group complete; next in flight
        } else {
            cp_wait<0>();
        }
        __syncthreads();           // publish current buffer (also WAR for reuse)

        const float* xs   = x_s[buf];
        const int4*  lsrc = (const int4*)(labels + (size_t)row * N_COLS);

        // ---- pass 1: gather x, exp, partial sums (staggered label loads) ----
        float ev[CHUNK];
        float acc_x;
        {
            int4 l0 = lsrc[4 * t + 0];
            int4 l1 = lsrc[4 * t + 1];
            float x0 = xs[l0.x], x1 = xs[l0.y], x2 = xs[l0.z], x3 = xs[l0.w];
            float x4 = xs[l1.x], x5 = xs[l1.y], x6 = xs[l1.z], x7 = xs[l1.w];
            acc_x = ((x0 + x1) + (x2 + x3)) + ((x4 + x5) + (x6 + x7));
            ev[0] = __expf(x0); ev[1] = __expf(x1);
            ev[2] = __expf(x2); ev[3] = __expf(x3);
            ev[4] = __expf(x4); ev[5] = __expf(x5);
            ev[6] = __expf(x6); ev[7] = __expf(x7);
        }
        {
            int4 l2 = lsrc[4 * t + 2];
            int4 l3 = lsrc[4 * t + 3];
            float x0 = xs[l2.x], x1 = xs[l2.y], x2 = xs[l2.z], x3 = xs[l2.w];
            float x4 = xs[l3.x], x5 = xs[l3.y], x6 = xs[l3.z], x7 = xs[l3.w];
            acc_x += ((x0 + x1) + (x2 + x3)) + ((x4 + x5) + (x6 + x7));
            ev[ 8] = __expf(x0); ev[ 9] = __expf(x1);
            ev[10] = __expf(x2); ev[11] = __expf(x3);
            ev[12] = __expf(x4); ev[13] = __expf(x5);
            ev[14] = __expf(x6); ev[15] = __expf(x7);
        }

        float tsum = 0.0f;
        #pragma unroll
        for (int i = 0; i < CHUNK; i += 4)
            tsum += ((ev[i] + ev[i + 1]) + (ev[i + 2] + ev[i + 3]));

        // ---- block exclusive add-scan over thread sums ----
        float incl = tsum;
        #pragma unroll
        for (int off = 1; off < 32; off <<= 1) {
            float v = __shfl_up_sync(full, incl, off);
            if (lane >= off) incl += v;
        }
        if (lane == 31) warp_tot[wid] = incl;
        __syncthreads();
        float woff = 0.0f;
        #pragma unroll
        for (int w = 0; w < NWARPS; w++)
            if (w < wid) woff += warp_tot[w];
        float excl = __shfl_up_sync(full, incl, 1);
        if (lane == 0) excl = 0.0f;
        float S = woff + excl;

        // ---- pass 2: running cumsum; fused log per group of 4 ----
        float acc2 = 0.0f;
        #pragma unroll
        for (int i = 0; i < CHUNK; i += 4) {
            float s0 = S + ev[i];
            float s1 = s0 + ev[i + 1];
            float s2 = s1 + ev[i + 2];
            float s3 = s2 + ev[i + 3];
            S = s3;
            float p = (s0 * s1) * (s2 * s3);   // < ~2.4e15, fp32-safe
            acc2 += __log2f(p);
        }
        float acc = acc2 * LN2F - acc_x;

        // ---- block reduce -> per-row partial ----
        #pragma unroll
        for (int off = 16; off > 0; off >>= 1)
            acc += __shfl_down_sync(full, acc, off);
        if (lane == 0) red_s[wid] = acc;
        __syncthreads();
        if (t == 0) {
            float bs = 0.0f;
            #pragma unroll
            for (int w = 0; w < NWARPS; w++) bs += red_s[w];
            g_partial[row] = bs;
        }
        // next iteration's top __syncthreads covers red_s/warp_tot WAR
    }

    // ---- block completion counter; last block reduces all rows ----
    __syncthreads();
    if (t == 0) {
        __threadfence();
        unsigned old = atomicAdd(&g_count, 1u);
        is_last = (old == (unsigned)(GRID - 1));
    }
    __syncthreads();

    if (is_last) {
        double a = 0.0;
        for (int i = t; i < B_ROWS; i += THREADS)
            a += (double)g_partial[i];
        #pragma unroll
        for (int off = 16; off > 0; off >>= 1)
            a += __shfl_down_sync(full, a, off);
        if (lane == 0) sd[wid] = a;
        __syncthreads();
        if (t == 0) {
            double s = 0.0;
            #pragma unroll
            for (int w = 0; w < NWARPS; w++) s += sd[w];
            out[0] = (float)(s / ((double)B_ROWS * (double)N_COLS));
            g_count = 0;   // reset for next graph replay
        }
    }
}

extern "C" void kernel_launch(void* const* d_in, const int* in_sizes, int n_in,
                              void* d_out, int out_size) {
    const float* outputs = (const float*)d_in[0];
    const int*   labels  = (const int*)d_in[1];
    float*       out     = (float*)d_out;
    (void)in_sizes; (void)n_in; (void)out_size;

    listmle_main<<<GRID, THREADS>>>(outputs, labels, out);
}

// round 12
// speedup vs baseline: 1.0614x; 1.0614x over previous
#include <cuda_runtime.h>
#include <cuda_fp16.h>

// ListMLE: B=8192 rows, N=4096, labels int32.
//   result = [ Σ_j log(S_j) - Σ x ] / (B*N),  S_j = cumsum_j exp(x[label[j]])
// Structure locked from round-8 evidence: 1 row/block, fp16 exp smem table
// (8 KB), regs<=32 -> 8 blocks/SM (two overlap experiments that traded
// occupancy both regressed). This round, occupancy-neutral shaves only:
//   - logs fused per 8 (prod of 8 prefix sums <= ~4e30, fp32-safe)
//   - __ldcs streaming loads (zero-reuse 256MB stream; evict-first)
// Fused deterministic finalize via fence+counter (fp64 fixed-order sum).

#define B_ROWS  8192
#define N_COLS  4096
#define THREADS 256
#define CHUNK   (N_COLS / THREADS)   // 16
#define NWARPS  (THREADS / 32)       // 8
#define LN2F    0.6931471805599453f

__device__ float        g_partial[B_ROWS];
__device__ unsigned int g_count = 0;

__global__ __launch_bounds__(THREADS, 8)
void listmle_main(const float* __restrict__ outputs,
                  const int* __restrict__ labels,
                  float* __restrict__ out) {
    __shared__ __half e_s[N_COLS];          // 8 KB: exp(x) as fp16
    __shared__ float  warp_tot[NWARPS];
    __shared__ float  red_s[NWARPS];
    __shared__ double sd[NWARPS];
    __shared__ bool   is_last;

    const int row  = blockIdx.x;
    const int t    = threadIdx.x;
    const int lane = t & 31;
    const int wid  = t >> 5;
    const unsigned full = 0xFFFFFFFFu;

    const int4* lsrc = (const int4*)(labels + (size_t)row * N_COLS);

    // ---- stage exp(outputs row) as packed 4xfp16 (STS.64); fold in sum(x) ----
    const float4* src4 = (const float4*)(outputs + (size_t)row * N_COLS);
    uint2* dst = (uint2*)e_s;               // one uint2 = 4 halves per float4
    float acc_x = 0.0f;
    #pragma unroll
    for (int k = 0; k < N_COLS / 4 / THREADS; k++) {   // 4 iterations
        float4 v = __ldcs(src4 + t + k * THREADS);     // streaming: no reuse
        acc_x += (v.x + v.y) + (v.z + v.w);
        __half2 h0 = __floats2half2_rn(__expf(v.x), __expf(v.y));
        __half2 h1 = __floats2half2_rn(__expf(v.z), __expf(v.w));
        uint2 pk;
        pk.x = *reinterpret_cast<unsigned*>(&h0);
        pk.y = *reinterpret_cast<unsigned*>(&h1);
        dst[t + k * THREADS] = pk;
    }
    __syncthreads();

    // ---- pass 1: gather fp16 exp values (staggered labels); partial sum ----
    float ev[CHUNK];
    {
        int4 l0 = __ldcs(lsrc + 4 * t + 0);
        int4 l1 = __ldcs(lsrc + 4 * t + 1);
        ev[0] = __half2float(e_s[l0.x]); ev[1] = __half2float(e_s[l0.y]);
        ev[2] = __half2float(e_s[l0.z]); ev[3] = __half2float(e_s[l0.w]);
        ev[4] = __half2float(e_s[l1.x]); ev[5] = __half2float(e_s[l1.y]);
        ev[6] = __half2float(e_s[l1.z]); ev[7] = __half2float(e_s[l1.w]);
    }
    {
        int4 l2 = __ldcs(lsrc + 4 * t + 2);
        int4 l3 = __ldcs(lsrc + 4 * t + 3);
        ev[ 8] = __half2float(e_s[l2.x]); ev[ 9] = __half2float(e_s[l2.y]);
        ev[10] = __half2float(e_s[l2.z]); ev[11] = __half2float(e_s[l2.w]);
        ev[12] = __half2float(e_s[l3.x]); ev[13] = __half2float(e_s[l3.y]);
        ev[14] = __half2float(e_s[l3.z]); ev[15] = __half2float(e_s[l3.w]);
    }

    float tsum = 0.0f;
    #pragma unroll
    for (int i = 0; i < CHUNK; i += 4)
        tsum += ((ev[i] + ev[i + 1]) + (ev[i + 2] + ev[i + 3]));

    // ---- block exclusive add-scan over thread sums ----
    float incl = tsum;
    #pragma unroll
    for (int off = 1; off < 32; off <<= 1) {
        float v = __shfl_up_sync(full, incl, off);
        if (lane >= off) incl += v;
    }
    if (lane == 31) warp_tot[wid] = incl;
    __syncthreads();

    float woff = 0.0f;                    // wid uniform within warp
    #pragma unroll
    for (int w = 0; w < NWARPS; w++)
        if (w < wid) woff += warp_tot[w];

    float excl = __shfl_up_sync(full, incl, 1);
    if (lane == 0) excl = 0.0f;
    float S = woff + excl;                // exclusive prefix of exp-sums

    // ---- pass 2: running cumsum; fused log per group of 8 ----
    float acc2 = 0.0f;
    #pragma unroll
    for (int i = 0; i < CHUNK; i += 8) {
        float s0 = S  + ev[i];
        float s1 = s0 + ev[i + 1];
        float s2 = s1 + ev[i + 2];
        float s3 = s2 + ev[i + 3];
        float s4 = s3 + ev[i + 4];
        float s5 = s4 + ev[i + 5];
        float s6 = s5 + ev[i + 6];
        float s7 = s6 + ev[i + 7];
        S = s7;
        float p = ((s0 * s1) * (s2 * s3)) * ((s4 * s5) * (s6 * s7)); // <= ~4e30
        acc2 += __log2f(p);
    }
    float acc = acc2 * LN2F - acc_x;

    // ---- block reduce -> per-row partial ----
    #pragma unroll
    for (int off = 16; off > 0; off >>= 1)
        acc += __shfl_down_sync(full, acc, off);
    if (lane == 0) red_s[wid] = acc;
    __syncthreads();
    if (t == 0) {
        float bs = 0.0f;
        #pragma unroll
        for (int w = 0; w < NWARPS; w++) bs += red_s[w];
        g_partial[row] = bs;
        __threadfence();
        unsigned old = atomicAdd(&g_count, 1u);
        is_last = (old == (unsigned)(gridDim.x - 1));
    }
    __syncthreads();

    // ---- last block: deterministic fp64 final reduction ----
    if (is_last) {
        double a = 0.0;
        for (int i = t; i < B_ROWS; i += THREADS)
            a += (double)g_partial[i];
        #pragma unroll
        for (int off = 16; off > 0; off >>= 1)
            a += __shfl_down_sync(full, a, off);
        if (lane == 0) sd[wid] = a;
        __syncthreads();
        if (t == 0) {
            double s = 0.0;
            #pragma unroll
            for (int w = 0; w < NWARPS; w++) s += sd[w];
            out[0] = (float)(s / ((double)B_ROWS * (double)N_COLS));
            g_count = 0;   // reset for next graph replay
        }
    }
}

extern "C" void kernel_launch(void* const* d_in, const int* in_sizes, int n_in,
                              void* d_out, int out_size) {
    const float* outputs = (const float*)d_in[0];
    const int*   labels  = (const int*)d_in[1];
    float*       out     = (float*)d_out;
    (void)in_sizes; (void)n_in; (void)out_size;

    listmle_main<<<B_ROWS, THREADS>>>(outputs, labels, out);
}

// round 13
// speedup vs baseline: 1.1977x; 1.1285x over previous
#include <cuda_runtime.h>

// ListMLE: B=8192 rows, N=4096, labels int32.
//   result = [ Σ_j log(S_j) - Σ x ] / (B*N),  S_j = cumsum_j exp(x[label[j]])
// Structure locked by rounds 8-11: 1 row/block, 256 thr, 8 blocks/SM; any
// occupancy traded for explicit overlap regressed. Round-13 (occupancy-
// neutral): stage the RAW fp32 row via cp.async.cg (register-free, no
// LDG+STS pair, no exp/pack in staging); exp after the gather. Logs fused
// per 4 (prod of 4 prefix sums < 2.4e15, fp32-safe). Σx from gathered set.
// Fused deterministic finalize via fence+counter (fp64 fixed-order sum).

#define B_ROWS  8192
#define N_COLS  4096
#define THREADS 256
#define CHUNK   (N_COLS / THREADS)   // 16
#define NWARPS  (THREADS / 32)       // 8
#define LN2F    0.6931471805599453f

__device__ float        g_partial[B_ROWS];
__device__ unsigned int g_count = 0;

__device__ __forceinline__ void cp16(unsigned dst, const void* src) {
    asm volatile("cp.async.cg.shared.global [%0], [%1], 16;" :: "r"(dst), "l"(src));
}

__global__ __launch_bounds__(THREADS, 8)
void listmle_main(const float* __restrict__ outputs,
                  const int* __restrict__ labels,
                  float* __restrict__ out) {
    __shared__ float  x_s[N_COLS];          // 16 KB: raw fp32 row
    __shared__ float  warp_tot[NWARPS];
    __shared__ float  red_s[NWARPS];
    __shared__ double sd[NWARPS];
    __shared__ bool   is_last;

    const int row  = blockIdx.x;
    const int t    = threadIdx.x;
    const int lane = t & 31;
    const int wid  = t >> 5;
    const unsigned full = 0xFFFFFFFFu;

    const int4* lsrc = (const int4*)(labels + (size_t)row * N_COLS);

    // ---- stage raw row via cp.async (no registers, no exp work here) ----
    {
        const char* src = (const char*)(outputs + (size_t)row * N_COLS);
        const unsigned sb = (unsigned)__cvta_generic_to_shared(x_s);
        #pragma unroll
        for (int k = 0; k < 4; k++) {
            unsigned off = (unsigned)(t + k * THREADS) * 16u;
            cp16(sb + off, src + off);
        }
        asm volatile("cp.async.commit_group;");
        asm volatile("cp.async.wait_group 0;");
    }
    __syncthreads();

    // ---- pass 1: gather x, sum x, exp -> ev (staggered label loads) ----
    float ev[CHUNK];
    float acc_x;
    {
        int4 l0 = lsrc[4 * t + 0];
        int4 l1 = lsrc[4 * t + 1];
        float x0 = x_s[l0.x], x1 = x_s[l0.y], x2 = x_s[l0.z], x3 = x_s[l0.w];
        float x4 = x_s[l1.x], x5 = x_s[l1.y], x6 = x_s[l1.z], x7 = x_s[l1.w];
        acc_x = ((x0 + x1) + (x2 + x3)) + ((x4 + x5) + (x6 + x7));
        ev[0] = __expf(x0); ev[1] = __expf(x1);
        ev[2] = __expf(x2); ev[3] = __expf(x3);
        ev[4] = __expf(x4); ev[5] = __expf(x5);
        ev[6] = __expf(x6); ev[7] = __expf(x7);
    }
    {
        int4 l2 = lsrc[4 * t + 2];
        int4 l3 = lsrc[4 * t + 3];
        float x0 = x_s[l2.x], x1 = x_s[l2.y], x2 = x_s[l2.z], x3 = x_s[l2.w];
        float x4 = x_s[l3.x], x5 = x_s[l3.y], x6 = x_s[l3.z], x7 = x_s[l3.w];
        acc_x += ((x0 + x1) + (x2 + x3)) + ((x4 + x5) + (x6 + x7));
        ev[ 8] = __expf(x0); ev[ 9] = __expf(x1);
        ev[10] = __expf(x2); ev[11] = __expf(x3);
        ev[12] = __expf(x4); ev[13] = __expf(x5);
        ev[14] = __expf(x6); ev[15] = __expf(x7);
    }

    float tsum = 0.0f;
    #pragma unroll
    for (int i = 0; i < CHUNK; i += 4)
        tsum += ((ev[i] + ev[i + 1]) + (ev[i + 2] + ev[i + 3]));

    // ---- block exclusive add-scan over thread sums ----
    float incl = tsum;
    #pragma unroll
    for (int off = 1; off < 32; off <<= 1) {
        float v = __shfl_up_sync(full, incl, off);
        if (lane >= off) incl += v;
    }
    if (lane == 31) warp_tot[wid] = incl;
    __syncthreads();

    float woff = 0.0f;                    // wid uniform within warp
    #pragma unroll
    for (int w = 0; w < NWARPS; w++)
        if (w < wid) woff += warp_tot[w];

    float excl = __shfl_up_sync(full, incl, 1);
    if (lane == 0) excl = 0.0f;
    float S = woff + excl;                // exclusive prefix of exp-sums

    // ---- pass 2: running cumsum; fused log per group of 4 ----
    float acc2 = 0.0f;
    #pragma unroll
    for (int i = 0; i < CHUNK; i += 4) {
        float s0 = S + ev[i];
        float s1 = s0 + ev[i + 1];
        float s2 = s1 + ev[i + 2];
        float s3 = s2 + ev[i + 3];
        S = s3;
        float p = (s0 * s1) * (s2 * s3);  // < ~2.4e15, fp32-safe
        acc2 += __log2f(p);
    }
    float acc = acc2 * LN2F - acc_x;

    // ---- block reduce -> per-row partial ----
    #pragma unroll
    for (int off = 16; off > 0; off >>= 1)
        acc += __shfl_down_sync(full, acc, off);
    if (lane == 0) red_s[wid] = acc;
    __syncthreads();
    if (t == 0) {
        float bs = 0.0f;
        #pragma unroll
        for (int w = 0; w < NWARPS; w++) bs += red_s[w];
        g_partial[row] = bs;
        __threadfence();
        unsigned old = atomicAdd(&g_count, 1u);
        is_last = (old == (unsigned)(gridDim.x - 1));
    }
    __syncthreads();

    // ---- last block: deterministic fp64 final reduction ----
    if (is_last) {
        double a = 0.0;
        for (int i = t; i < B_ROWS; i += THREADS)
            a += (double)g_partial[i];
        #pragma unroll
        for (int off = 16; off > 0; off >>= 1)
            a += __shfl_down_sync(full, a, off);
        if (lane == 0) sd[wid] = a;
        __syncthreads();
        if (t == 0) {
            double s = 0.0;
            #pragma unroll
            for (int w = 0; w < NWARPS; w++) s += sd[w];
            out[0] = (float)(s / ((double)B_ROWS * (double)N_COLS));
            g_count = 0;   // reset for next graph replay
        }
    }
}

extern "C" void kernel_launch(void* const* d_in, const int* in_sizes, int n_in,
                              void* d_out, int out_size) {
    const float* outputs = (const float*)d_in[0];
    const int*   labels  = (const int*)d_in[1];
    float*       out     = (float*)d_out;
    (void)in_sizes; (void)n_in; (void)out_size;

    listmle_main<<<B_ROWS, THREADS>>>(outputs, labels, out);
}